// round 1
// baseline (speedup 1.0000x reference)
#include <cuda_runtime.h>
#include <math.h>

#define B_    8
#define TS    2
#define SEQ   720
#define ENC   862
#define MARKD 4
#define NTOK  866
#define D     256
#define NH    8
#define EH    32
#define DFF   512
#define DB    720
#define LAYERS 2
#define EPS   1e-5f
#define MROWS (B_*NTOK)   // 6928

// ---------------- scratch (device globals; no allocation) ----------------
__device__ float g_xin [(size_t)MROWS*SEQ];
__device__ float g_mean[B_*ENC];
__device__ float g_std [B_*ENC];
__device__ float g_h   [(size_t)MROWS*D];
__device__ float g_qkv [(size_t)3*MROWS*D];
__device__ float g_att [(size_t)MROWS*D];
__device__ float g_xatt[(size_t)MROWS*D];
__device__ float g_xln [(size_t)MROWS*D];
__device__ float g_y1  [(size_t)MROWS*DFF];
__device__ float g_y   [(size_t)MROWS*D];
__device__ float g_xs  [(size_t)MROWS*D];
__device__ float g_hh  [(size_t)MROWS*D];
__device__ float g_cat [(size_t)MROWS*2*D];
__device__ float g_o56 [(size_t)2*MROWS*DB];
__device__ float g_out [(size_t)MROWS*DB];
__device__ float g_scores[(size_t)B_*NH*NTOK*NTOK];   // 192 MB

// ---------------- reductions ----------------
__device__ __forceinline__ float blockReduce(float v, bool domax){
    __shared__ float sh[33];
    int lane = threadIdx.x & 31, wid = threadIdx.x >> 5;
    __syncthreads();
    #pragma unroll
    for (int o = 16; o; o >>= 1){
        float ov = __shfl_down_sync(0xffffffffu, v, o);
        v = domax ? fmaxf(v, ov) : (v + ov);
    }
    if (lane == 0) sh[wid] = v;
    __syncthreads();
    if (wid == 0){
        int nw = blockDim.x >> 5;
        v = (lane < nw) ? sh[lane] : (domax ? -1e30f : 0.f);
        #pragma unroll
        for (int o = 16; o; o >>= 1){
            float ov = __shfl_down_sync(0xffffffffu, v, o);
            v = domax ? fmaxf(v, ov) : (v + ov);
        }
        if (lane == 0) sh[32] = v;
    }
    __syncthreads();
    return sh[32];
}

// ---------------- input standardization stats ----------------
__global__ void stats_kernel(const float* __restrict__ mbx, int t){
    int b = blockIdx.y;
    int n = blockIdx.x * blockDim.x + threadIdx.x;
    if (n >= ENC) return;
    const float* base = mbx + ((size_t)(b*TS + t)*SEQ)*ENC + n;
    float s = 0.f, ss = 0.f;
    for (int i = 0; i < SEQ; i++){
        float v = base[(size_t)i*ENC];
        s += v; ss += v*v;
    }
    float m = s * (1.f/SEQ);
    float var = ss * (1.f/SEQ) - m*m;
    g_mean[b*ENC + n] = m;
    g_std [b*ENC + n] = sqrtf(var + EPS);
}

// ---------------- build xin [B, NTOK, SEQ] ----------------
__global__ void xin_kernel(const float* __restrict__ mbx,
                           const float* __restrict__ mbxm, int t){
    size_t total = (size_t)B_*NTOK*SEQ;
    size_t idx = (size_t)blockIdx.x*blockDim.x + threadIdx.x;
    if (idx >= total) return;
    int s = (int)(idx % SEQ);
    size_t r = idx / SEQ;
    int n = (int)(r % NTOK);
    int b = (int)(r / NTOK);
    float v;
    if (n < ENC){
        v = mbx[((size_t)(b*TS + t)*SEQ + s)*ENC + n];
        v = (v - g_mean[b*ENC + n]) / g_std[b*ENC + n];
    } else {
        v = mbxm[((size_t)(b*TS + t)*SEQ + s)*MARKD + (n - ENC)];
    }
    g_xin[idx] = v;
}

// ---------------- generic batched GEMM: C = A @ W^T + bias ----------------
struct GemmArgs {
    const float* A[3];
    const float* W[3];
    const float* Bv[3];
    float*       C[3];
};

template<int ACT>  // 0: none, 1: exact gelu
__global__ __launch_bounds__(256)
void gemm_kernel(GemmArgs p, int M, int N, int K){
    const int z = blockIdx.z;
    const float* __restrict__ A    = p.A[z];
    const float* __restrict__ W    = p.W[z];
    const float* __restrict__ bias = p.Bv[z];
    float*       __restrict__ C    = p.C[z];

    __shared__ float As[8][128];
    __shared__ float Bs[8][128];
    const int bm = blockIdx.y * 128, bn = blockIdx.x * 128;
    const int tid  = threadIdx.x;
    const int lRow = tid >> 1;
    const int lCol = (tid & 1) << 2;
    const int tr = tid >> 4, tc = tid & 15;

    float acc[8][8] = {};

    for (int k0 = 0; k0 < K; k0 += 8){
        float4 a4 = make_float4(0.f,0.f,0.f,0.f);
        int am = bm + lRow;
        if (am < M) a4 = *(const float4*)(A + (size_t)am*K + k0 + lCol);
        As[lCol+0][lRow] = a4.x; As[lCol+1][lRow] = a4.y;
        As[lCol+2][lRow] = a4.z; As[lCol+3][lRow] = a4.w;

        float4 b4 = make_float4(0.f,0.f,0.f,0.f);
        int wn = bn + lRow;
        if (wn < N) b4 = *(const float4*)(W + (size_t)wn*K + k0 + lCol);
        Bs[lCol+0][lRow] = b4.x; Bs[lCol+1][lRow] = b4.y;
        Bs[lCol+2][lRow] = b4.z; Bs[lCol+3][lRow] = b4.w;
        __syncthreads();

        #pragma unroll
        for (int kk = 0; kk < 8; kk++){
            float ra[8], rb[8];
            #pragma unroll
            for (int i = 0; i < 8; i++) ra[i] = As[kk][tr*8 + i];
            #pragma unroll
            for (int j = 0; j < 8; j++) rb[j] = Bs[kk][tc*8 + j];
            #pragma unroll
            for (int i = 0; i < 8; i++)
                #pragma unroll
                for (int j = 0; j < 8; j++)
                    acc[i][j] += ra[i]*rb[j];
        }
        __syncthreads();
    }

    #pragma unroll
    for (int i = 0; i < 8; i++){
        int row = bm + tr*8 + i;
        if (row >= M) continue;
        #pragma unroll
        for (int j = 0; j < 8; j++){
            int col = bn + tc*8 + j;
            if (col < N){
                float c = acc[i][j] + bias[col];
                if (ACT == 1) c = 0.5f*c*(1.f + erff(c*0.70710678118654752f));
                C[(size_t)row*N + col] = c;
            }
        }
    }
}

// ---------------- attention: scores = scale * Q K^T ----------------
__global__ __launch_bounds__(256) void scores_kernel(){
    const int bh = blockIdx.z;
    const int b = bh / NH, h = bh % NH;
    const int i0 = blockIdx.y * 64, j0 = blockIdx.x * 64;
    __shared__ float Qs[64][33];
    __shared__ float Ks[64][33];
    const float* q = g_qkv + ((size_t)b*NTOK)*D + h*EH;
    const float* k = g_qkv + (size_t)MROWS*D + ((size_t)b*NTOK)*D + h*EH;

    for (int idx = threadIdx.x; idx < 64*32; idx += 256){
        int r = idx >> 5, e = idx & 31;
        int gi = i0 + r, gj = j0 + r;
        Qs[r][e] = (gi < NTOK) ? q[(size_t)gi*D + e] : 0.f;
        Ks[r][e] = (gj < NTOK) ? k[(size_t)gj*D + e] : 0.f;
    }
    __syncthreads();

    const int tr = threadIdx.x >> 4, tc = threadIdx.x & 15;
    float acc[4][4] = {};
    #pragma unroll
    for (int e = 0; e < 32; e++){
        float ra[4], rb[4];
        #pragma unroll
        for (int i = 0; i < 4; i++) ra[i] = Qs[tr*4 + i][e];
        #pragma unroll
        for (int j = 0; j < 4; j++) rb[j] = Ks[tc*4 + j][e];
        #pragma unroll
        for (int i = 0; i < 4; i++)
            #pragma unroll
            for (int j = 0; j < 4; j++) acc[i][j] += ra[i]*rb[j];
    }

    float* S = g_scores + (size_t)bh*NTOK*NTOK;
    const float scale = 0.17677669529663688f;  // 1/sqrt(32)
    #pragma unroll
    for (int i = 0; i < 4; i++){
        int gi = i0 + tr*4 + i;
        if (gi >= NTOK) continue;
        #pragma unroll
        for (int j = 0; j < 4; j++){
            int gj = j0 + tc*4 + j;
            if (gj < NTOK) S[(size_t)gi*NTOK + gj] = acc[i][j]*scale;
        }
    }
}

// ---------------- softmax over last dim (rows of 866) ----------------
__global__ __launch_bounds__(128) void softmax_kernel(){
    size_t row = blockIdx.x;
    float* p = g_scores + row*(size_t)NTOK;
    float v[7];
    float mx = -1e30f;
    #pragma unroll
    for (int i = 0; i < 7; i++){
        int j = threadIdx.x + i*128;
        v[i] = (j < NTOK) ? p[j] : -1e30f;
        mx = fmaxf(mx, v[i]);
    }
    mx = blockReduce(mx, true);
    float sum = 0.f;
    #pragma unroll
    for (int i = 0; i < 7; i++){
        v[i] = expf(v[i] - mx);   // invalid lanes -> exp(very negative) = 0
        sum += v[i];
    }
    sum = blockReduce(sum, false);
    float inv = 1.f / sum;
    #pragma unroll
    for (int i = 0; i < 7; i++){
        int j = threadIdx.x + i*128;
        if (j < NTOK) p[j] = v[i]*inv;
    }
}

// ---------------- att = P @ V ----------------
__global__ __launch_bounds__(256) void av_kernel(){
    const int bh = blockIdx.y;
    const int b = bh / NH, h = bh % NH;
    const int i0 = blockIdx.x * 64;
    __shared__ float Ps[64][65];
    __shared__ float Vs[64][33];
    const float* S = g_scores + (size_t)bh*NTOK*NTOK;
    const float* v = g_qkv + (size_t)2*MROWS*D + ((size_t)b*NTOK)*D + h*EH;
    const int lane = threadIdx.x & 31, rbase = threadIdx.x >> 5;
    float acc[8] = {};

    for (int j0 = 0; j0 < NTOK; j0 += 64){
        for (int idx = threadIdx.x; idx < 64*64; idx += 256){
            int li = idx >> 6, lj = idx & 63;
            int gi = i0 + li, gj = j0 + lj;
            Ps[li][lj] = (gi < NTOK && gj < NTOK) ? S[(size_t)gi*NTOK + gj] : 0.f;
        }
        for (int idx = threadIdx.x; idx < 64*32; idx += 256){
            int lj = idx >> 5, e = idx & 31;
            int gj = j0 + lj;
            Vs[lj][e] = (gj < NTOK) ? v[(size_t)gj*D + e] : 0.f;
        }
        __syncthreads();
        #pragma unroll
        for (int lj = 0; lj < 64; lj++){
            float vv = Vs[lj][lane];
            #pragma unroll
            for (int r = 0; r < 8; r++) acc[r] += Ps[rbase + r*8][lj]*vv;
        }
        __syncthreads();
    }
    #pragma unroll
    for (int r = 0; r < 8; r++){
        int gi = i0 + rbase + r*8;
        if (gi < NTOK) g_att[((size_t)b*NTOK + gi)*D + h*EH + lane] = acc[r];
    }
}

// ---------------- LayerNorm(x [- sub]) over D=256 ----------------
__global__ __launch_bounds__(256) void ln_kernel(const float* __restrict__ X,
                                                 const float* __restrict__ Sub,
                                                 const float* __restrict__ g,
                                                 const float* __restrict__ beta,
                                                 float* __restrict__ Out){
    int row = blockIdx.x, d = threadIdx.x;
    size_t i = (size_t)row*D + d;
    float v = X[i] - (Sub ? Sub[i] : 0.f);
    float mean = blockReduce(v, false) * (1.f/D);
    float dv = v - mean;
    float var = blockReduce(dv*dv, false) * (1.f/D);
    Out[i] = dv * rsqrtf(var + EPS) * g[d] + beta[d];
}

// ---------------- elementwise fusion kernels ----------------
__global__ void sub_kernel(const float* __restrict__ a, const float* __restrict__ b,
                           float* __restrict__ c, size_t n){
    size_t i = (size_t)blockIdx.x*blockDim.x + threadIdx.x;
    if (i < n) c[i] = a[i] - b[i];
}

__global__ void glu_kernel(const float* __restrict__ a, const float* __restrict__ b,
                           float* __restrict__ c, size_t n){
    size_t i = (size_t)blockIdx.x*blockDim.x + threadIdx.x;
    if (i < n) c[i] = (1.f/(1.f + expf(-a[i]))) * b[i];
}

__global__ void cat_kernel(const float* __restrict__ xatt, const float* __restrict__ y){
    size_t n = (size_t)MROWS*2*D;
    size_t i = (size_t)blockIdx.x*blockDim.x + threadIdx.x;
    if (i >= n) return;
    int c = (int)(i % (2*D));
    size_t r = i / (2*D);
    g_cat[i] = (c < D) ? xatt[r*D + c] : y[r*D + c - D];
}

__global__ void outcomb_kernel(int l){
    size_t n = (size_t)MROWS*DB;
    size_t i = (size_t)blockIdx.x*blockDim.x + threadIdx.x;
    if (i >= n) return;
    float a = g_o56[i], b = g_o56[n + i];
    float v = (1.f/(1.f + expf(-a))) * b;
    g_out[i] = l ? (v - g_out[i]) : v;
}

// ---------------- final: de-standardize, transpose, 2-scale mean ----------------
__global__ void final_kernel(float* __restrict__ out, int t){
    size_t total = (size_t)B_*DB*ENC;
    size_t idx = (size_t)blockIdx.x*blockDim.x + threadIdx.x;
    if (idx >= total) return;
    int n = (int)(idx % ENC);
    size_t r = idx / ENC;
    int p = (int)(r % DB);
    int b = (int)(r / DB);
    float v = g_out[((size_t)b*NTOK + n)*DB + p] * g_std[b*ENC + n] + g_mean[b*ENC + n];
    v *= 0.5f;
    if (t == 0) out[idx] = v; else out[idx] += v;
}

// ---------------- host ----------------
static inline GemmArgs ga1(const float* A, const float* W, const float* b, float* C){
    GemmArgs g = {};
    g.A[0] = A; g.W[0] = W; g.Bv[0] = b; g.C[0] = C;
    return g;
}

extern "C" void kernel_launch(void* const* d_in, const int* in_sizes, int n_in,
                              void* d_out, int out_size){
    const float* mbx  = (const float*)d_in[0];
    const float* mbxm = (const float*)d_in[1];
    const float* embW = (const float*)d_in[4];
    const float* embB = (const float*)d_in[5];
    const float* Wq = (const float*)d_in[6];
    const float* Wk = (const float*)d_in[7];
    const float* Wv = (const float*)d_in[8];
    const float* Wo = (const float*)d_in[9];
    const float* W3 = (const float*)d_in[10];
    const float* W4 = (const float*)d_in[11];
    const float* bq = (const float*)d_in[12];
    const float* bk = (const float*)d_in[13];
    const float* bv = (const float*)d_in[14];
    const float* bo = (const float*)d_in[15];
    const float* b3 = (const float*)d_in[16];
    const float* b4 = (const float*)d_in[17];
    const float* W1 = (const float*)d_in[18];
    const float* b1 = (const float*)d_in[19];
    const float* W2 = (const float*)d_in[20];
    const float* b2 = (const float*)d_in[21];
    const float* W5 = (const float*)d_in[22];
    const float* b5 = (const float*)d_in[23];
    const float* W6 = (const float*)d_in[24];
    const float* b6 = (const float*)d_in[25];
    const float* ln1g = (const float*)d_in[26];
    const float* ln1b = (const float*)d_in[27];
    const float* ln2g = (const float*)d_in[28];
    const float* ln2b = (const float*)d_in[29];
    float* out = (float*)d_out;

    float *xin, *h, *qkv, *att, *xatt, *xln, *y1, *y, *xs, *hh, *cat, *o56;
    cudaGetSymbolAddress((void**)&xin,  g_xin);
    cudaGetSymbolAddress((void**)&h,    g_h);
    cudaGetSymbolAddress((void**)&qkv,  g_qkv);
    cudaGetSymbolAddress((void**)&att,  g_att);
    cudaGetSymbolAddress((void**)&xatt, g_xatt);
    cudaGetSymbolAddress((void**)&xln,  g_xln);
    cudaGetSymbolAddress((void**)&y1,   g_y1);
    cudaGetSymbolAddress((void**)&y,    g_y);
    cudaGetSymbolAddress((void**)&xs,   g_xs);
    cudaGetSymbolAddress((void**)&hh,   g_hh);
    cudaGetSymbolAddress((void**)&cat,  g_cat);
    cudaGetSymbolAddress((void**)&o56,  g_o56);

    const size_t MD = (size_t)MROWS*D;
    const int mTiles = (MROWS + 127)/128;   // 55

    for (int t = 0; t < TS; t++){
        stats_kernel<<<dim3((ENC + 255)/256, B_), 256>>>(mbx, t);
        {
            size_t n = (size_t)B_*NTOK*SEQ;
            xin_kernel<<<(unsigned)((n + 255)/256), 256>>>(mbx, mbxm, t);
        }
        gemm_kernel<0><<<dim3((D + 127)/128, mTiles, 1), 256>>>(
            ga1(xin, embW, embB, h), MROWS, D, SEQ);

        for (int l = 0; l < LAYERS; l++){
            // Q, K, V in one launch
            GemmArgs q3 = {};
            q3.A[0] = h; q3.A[1] = h; q3.A[2] = h;
            q3.W[0] = Wq + (size_t)l*D*D; q3.W[1] = Wk + (size_t)l*D*D; q3.W[2] = Wv + (size_t)l*D*D;
            q3.Bv[0] = bq + l*D; q3.Bv[1] = bk + l*D; q3.Bv[2] = bv + l*D;
            q3.C[0] = qkv; q3.C[1] = qkv + MD; q3.C[2] = qkv + 2*MD;
            gemm_kernel<0><<<dim3(2, mTiles, 3), 256>>>(q3, MROWS, D, D);

            scores_kernel<<<dim3(14, 14, B_*NH), 256>>>();
            softmax_kernel<<<B_*NH*NTOK, 128>>>();
            av_kernel<<<dim3(14, B_*NH), 256>>>();

            gemm_kernel<0><<<dim3(2, mTiles, 1), 256>>>(
                ga1(att, Wo + (size_t)l*D*D, bo + l*D, xatt), MROWS, D, D);

            ln_kernel<<<MROWS, 256>>>(h, xatt, ln1g + l*D, ln1b + l*D, xln);

            gemm_kernel<1><<<dim3(4, mTiles, 1), 256>>>(
                ga1(xln, W1 + (size_t)l*DFF*D, b1 + l*DFF, y1), MROWS, DFF, D);
            gemm_kernel<0><<<dim3(2, mTiles, 1), 256>>>(
                ga1(y1, W2 + (size_t)l*D*DFF, b2 + l*D, y), MROWS, D, DFF);

            sub_kernel<<<(unsigned)((MD + 255)/256), 256>>>(xln, y, xs, MD);

            GemmArgs g34 = {};
            g34.A[0] = xs; g34.A[1] = xs;
            g34.W[0] = W3 + (size_t)l*D*D; g34.W[1] = W4 + (size_t)l*D*D;
            g34.Bv[0] = b3 + l*D; g34.Bv[1] = b4 + l*D;
            g34.C[0] = qkv; g34.C[1] = qkv + MD;   // reuse q/k slots
            gemm_kernel<0><<<dim3(2, mTiles, 2), 256>>>(g34, MROWS, D, D);

            glu_kernel<<<(unsigned)((MD + 255)/256), 256>>>(qkv, qkv + MD, hh, MD);
            cat_kernel<<<(unsigned)(((size_t)MROWS*2*D + 255)/256), 256>>>(xatt, y);

            GemmArgs g56 = {};
            g56.A[0] = cat; g56.A[1] = cat;
            g56.W[0] = W5 + (size_t)l*DB*2*D; g56.W[1] = W6 + (size_t)l*DB*2*D;
            g56.Bv[0] = b5 + l*DB; g56.Bv[1] = b6 + l*DB;
            g56.C[0] = o56; g56.C[1] = o56 + (size_t)MROWS*DB;
            gemm_kernel<0><<<dim3((DB + 127)/128, mTiles, 2), 256>>>(g56, MROWS, DB, 2*D);

            outcomb_kernel<<<(unsigned)(((size_t)MROWS*DB + 255)/256), 256>>>(l);

            ln_kernel<<<MROWS, 256>>>(hh, (const float*)nullptr, ln2g + l*D, ln2b + l*D, h);
        }

        final_kernel<<<(unsigned)(((size_t)B_*DB*ENC + 255)/256), 256>>>(out, t);
    }
}